// round 1
// baseline (speedup 1.0000x reference)
#include <cuda_runtime.h>

// FlashAttention for B=2, H=16, S=2048, D=64, fp32 + int32 mask.
// Baseline: CUDA-core fp32 flash attention using packed fma.rn.f32x2
// (sm_103a 2x-rate fp32) for both QK^T and PV.

namespace {
constexpr int B = 2, H = 16, S = 2048, Dh = 64;
constexpr int BQ = 128, BK = 64;
constexpr int TX = 16, TY = 16, NTHREADS = TX * TY;  // 256
constexpr int QPT = BQ / TY;   // 8 q-rows per thread
constexpr float SCALE = 0.125f;          // 1/sqrt(64)
constexpr float NEG_INF_F = -1e30f;

constexpr int SQT = Dh * BQ;             // Q transposed: [d][q]   8192 f
constexpr int SKT = Dh * BK;             // K transposed: [d][k]   4096 f
constexpr int SVV = BK * Dh;             // V:            [k][d]   4096 f
constexpr int PSTRIDE = BK + 1;          // 65 (conflict-free column reads)
constexpr int SPP = BQ * PSTRIDE;        // P:            [q][k]   8320 f
constexpr int SMEM_FLOATS = SQT + SKT + SVV + SPP;   // 24704 f = 98816 B
}  // namespace

__device__ __forceinline__ unsigned long long pk2(float x, float y) {
    unsigned long long r;
    asm("mov.b64 %0, {%1, %2};" : "=l"(r) : "f"(x), "f"(y));
    return r;
}
__device__ __forceinline__ void upk2(unsigned long long v, float& x, float& y) {
    asm("mov.b64 {%0, %1}, %2;" : "=f"(x), "=f"(y) : "l"(v));
}
__device__ __forceinline__ unsigned long long fma2(unsigned long long a,
                                                   unsigned long long b,
                                                   unsigned long long c) {
    unsigned long long d;
    asm("fma.rn.f32x2 %0, %1, %2, %3;" : "=l"(d) : "l"(a), "l"(b), "l"(c));
    return d;
}
__device__ __forceinline__ unsigned long long mul2(unsigned long long a,
                                                   unsigned long long b) {
    unsigned long long d;
    asm("mul.rn.f32x2 %0, %1, %2;" : "=l"(d) : "l"(a), "l"(b));
    return d;
}

__global__ void __launch_bounds__(NTHREADS, 2)
fa_f32x2_kernel(const float* __restrict__ Q, const float* __restrict__ K,
                const float* __restrict__ V, const int* __restrict__ M,
                float* __restrict__ O) {
    extern __shared__ float sm[];
    float* sQt = sm;                 // [Dh][BQ]
    float* sKt = sQt + SQT;          // [Dh][BK]
    float* sV  = sKt + SKT;          // [BK][Dh]
    float* sP  = sV + SVV;           // [BQ][PSTRIDE]

    const int tid = threadIdx.x;
    const int tx = tid & 15;         // k / d column group
    const int ty = tid >> 4;         // q row group
    const int q0 = blockIdx.x * BQ;
    const int bh = blockIdx.y;

    const float* Qg = Q + (size_t)bh * S * Dh + (size_t)q0 * Dh;
    const float* Kg = K + (size_t)bh * S * Dh;
    const float* Vg = V + (size_t)bh * S * Dh;
    const int*   Mg = M + (size_t)bh * S * S + (size_t)q0 * S;

    // Load Q tile, transposed to [d][q] (broadcast-friendly reads in QK).
    #pragma unroll
    for (int i = tid; i < BQ * Dh; i += NTHREADS) {
        int q = i >> 6, d = i & 63;
        sQt[d * BQ + q] = Qg[i];
    }

    float mrow[QPT], lrow[QPT];
    unsigned long long acc[QPT][2];  // O accumulator, 4 d-cols as 2x f32x2
    #pragma unroll
    for (int r = 0; r < QPT; ++r) {
        mrow[r] = NEG_INF_F;
        lrow[r] = 0.0f;
        acc[r][0] = 0ull;
        acc[r][1] = 0ull;
    }

    for (int kt = 0; kt < S / BK; ++kt) {
        __syncthreads();  // previous tile's sKt/sV/sP reads complete

        // Load K tile transposed to [d][k]; V tile as [k][d] (float4).
        const float* Ktg = Kg + kt * BK * Dh;
        #pragma unroll
        for (int i = tid; i < BK * Dh; i += NTHREADS) {
            int k = i >> 6, d = i & 63;
            sKt[d * BK + k] = Ktg[i];
        }
        const float4* Vtg = (const float4*)(Vg + (size_t)kt * BK * Dh);
        float4* sV4 = (float4*)sV;
        #pragma unroll
        for (int i = tid; i < BK * Dh / 4; i += NTHREADS) sV4[i] = Vtg[i];
        __syncthreads();

        // ---- S = Q @ K^T (raw dot; scale applied later) ----
        unsigned long long s2[QPT][2];
        #pragma unroll
        for (int r = 0; r < QPT; ++r) { s2[r][0] = 0ull; s2[r][1] = 0ull; }

        #pragma unroll 4
        for (int d = 0; d < Dh; ++d) {
            // two k-pairs, contiguous in sKt -> direct 64-bit loads
            unsigned long long k0 =
                *(const unsigned long long*)&sKt[d * BK + tx * 4];
            unsigned long long k1 =
                *(const unsigned long long*)&sKt[d * BK + tx * 4 + 2];
            const float* qcol = &sQt[d * BQ + ty * QPT];
            #pragma unroll
            for (int r = 0; r < QPT; ++r) {
                float qv = qcol[r];
                unsigned long long q2 = pk2(qv, qv);
                s2[r][0] = fma2(q2, k0, s2[r][0]);
                s2[r][1] = fma2(q2, k1, s2[r][1]);
            }
        }

        // ---- mask + online softmax (row state per q-row) ----
        const int* Mtile = Mg + kt * BK;
        #pragma unroll
        for (int r = 0; r < QPT; ++r) {
            int q = ty * QPT + r;
            int4 mk = *(const int4*)&Mtile[(size_t)q * S + tx * 4];
            float v0, v1, v2, v3;
            upk2(s2[r][0], v0, v1);
            upk2(s2[r][1], v2, v3);
            v0 = (mk.x == 0) ? NEG_INF_F : v0 * SCALE;
            v1 = (mk.y == 0) ? NEG_INF_F : v1 * SCALE;
            v2 = (mk.z == 0) ? NEG_INF_F : v2 * SCALE;
            v3 = (mk.w == 0) ? NEG_INF_F : v3 * SCALE;

            float mx = fmaxf(fmaxf(v0, v1), fmaxf(v2, v3));
            #pragma unroll
            for (int o = 8; o >= 1; o >>= 1)
                mx = fmaxf(mx, __shfl_xor_sync(0xffffffffu, mx, o, 16));
            float mnew = fmaxf(mrow[r], mx);
            float alpha = __expf(mrow[r] - mnew);
            float p0 = __expf(v0 - mnew);
            float p1 = __expf(v1 - mnew);
            float p2 = __expf(v2 - mnew);
            float p3 = __expf(v3 - mnew);
            float ls = (p0 + p1) + (p2 + p3);
            #pragma unroll
            for (int o = 8; o >= 1; o >>= 1)
                ls += __shfl_xor_sync(0xffffffffu, ls, o, 16);
            lrow[r] = lrow[r] * alpha + ls;
            mrow[r] = mnew;

            unsigned long long a2 = pk2(alpha, alpha);
            acc[r][0] = mul2(acc[r][0], a2);
            acc[r][1] = mul2(acc[r][1], a2);

            float* prow = &sP[q * PSTRIDE + tx * 4];
            prow[0] = p0; prow[1] = p1; prow[2] = p2; prow[3] = p3;
        }
        __syncthreads();

        // ---- O += P @ V ----
        #pragma unroll 4
        for (int k = 0; k < BK; ++k) {
            unsigned long long w0 =
                *(const unsigned long long*)&sV[k * Dh + tx * 4];
            unsigned long long w1 =
                *(const unsigned long long*)&sV[k * Dh + tx * 4 + 2];
            const float* pcol = &sP[ty * QPT * PSTRIDE + k];
            #pragma unroll
            for (int r = 0; r < QPT; ++r) {
                float pv = pcol[r * PSTRIDE];
                unsigned long long p2 = pk2(pv, pv);
                acc[r][0] = fma2(p2, w0, acc[r][0]);
                acc[r][1] = fma2(p2, w1, acc[r][1]);
            }
        }
    }

    // ---- epilogue: O / l ----
    float* Og = O + (size_t)bh * S * Dh + (size_t)q0 * Dh;
    #pragma unroll
    for (int r = 0; r < QPT; ++r) {
        float inv = 1.0f / lrow[r];
        float o0, o1, o2, o3;
        upk2(acc[r][0], o0, o1);
        upk2(acc[r][1], o2, o3);
        float4 ov = make_float4(o0 * inv, o1 * inv, o2 * inv, o3 * inv);
        *(float4*)&Og[(ty * QPT + r) * Dh + tx * 4] = ov;
    }
}

extern "C" void kernel_launch(void* const* d_in, const int* in_sizes, int n_in,
                              void* d_out, int out_size) {
    const float* Q = (const float*)d_in[0];
    const float* K = (const float*)d_in[1];
    const float* V = (const float*)d_in[2];
    const int*   M = (const int*)d_in[3];
    float* O = (float*)d_out;

    (void)in_sizes; (void)n_in; (void)out_size;

    cudaFuncSetAttribute(fa_f32x2_kernel,
                         cudaFuncAttributeMaxDynamicSharedMemorySize,
                         SMEM_FLOATS * (int)sizeof(float));

    dim3 grid(S / BQ, B * H);
    fa_f32x2_kernel<<<grid, NTHREADS, SMEM_FLOATS * sizeof(float)>>>(Q, K, V, M, O);
}